// round 16
// baseline (speedup 1.0000x reference)
#include <cuda_runtime.h>

#define TT  50
#define BB  2048
#define NLS 5
#define WPB 2

__device__ float g_taus[NLS * TT * BB * 16];  // [a][t][b][16]

// ---- per-warp smem layout (float offsets) ----
#define OFF_F    0
#define OFF_V    240
#define OFF_v    384
#define OFF_QXU  416
#define OFF_QXB  464
#define OFF_QUU  480
#define OFF_RF   656
// rollout overlays
#define OFF_C    240
#define OFF_c    560
#define OFF_f    576
#define OFF_TAU  592    // 80 [a][16]: x state lives in slots 0..11, u in 12..15
// persistent
#define OFF_UN   736
#define OFF_K    936
#define WF       3536

struct RPre { float4 F0, F1, f4, ca, cb; float cj; };

__device__ __forceinline__ void r_load(RPre& p,
    const float* __restrict__ gC, const float* __restrict__ gc,
    const float* __restrict__ gF, const float* __restrict__ gf,
    int base, int lane, int h, int j)
{
    const float4* F4 = reinterpret_cast<const float4*>(gF) + (size_t)base * 48;
    p.F0 = F4[lane];
    if (lane < 16) p.F1 = F4[lane + 32];
    const float4* C4 = reinterpret_cast<const float4*>(gC) + (size_t)base * 64;
    p.ca = C4[j * 4 + h * 2];
    p.cb = C4[j * 4 + h * 2 + 1];
    p.cj = gc[(size_t)base * 16 + j];
    if (lane < 3) p.f4 = reinterpret_cast<const float4*>(gf + (size_t)base * 12)[lane];
}

struct FPre { float4 C0, C1, F0, F1, c4, f4; };

__device__ __forceinline__ void f_load(FPre& p,
    const float* __restrict__ gC, const float* __restrict__ gc,
    const float* __restrict__ gF, const float* __restrict__ gf,
    int base, int lane)
{
    const float4* C4 = reinterpret_cast<const float4*>(gC) + (size_t)base * 64;
    p.C0 = C4[lane];
    p.C1 = C4[lane + 32];
    const float4* F4 = reinterpret_cast<const float4*>(gF) + (size_t)base * 48;
    p.F0 = F4[lane];
    if (lane < 16) p.F1 = F4[lane + 32];
    if (lane < 4)  p.c4 = reinterpret_cast<const float4*>(gc)[(size_t)base * 4 + lane];
    if (lane < 3)  p.f4 = reinterpret_cast<const float4*>(gf + (size_t)base * 12)[lane];
}

__global__ void __launch_bounds__(32 * WPB, 7) ilqr_fused_kernel(
    const float* __restrict__ gC, const float* __restrict__ gc,
    const float* __restrict__ gF, const float* __restrict__ gf,
    const float* __restrict__ gx0, float* __restrict__ out)
{
    __shared__ __align__(16) float smem[WPB][WF];
    const int w    = threadIdx.x >> 5;
    const int lane = threadIdx.x & 31;
    const int b    = blockIdx.x * WPB + w;
    const int j    = lane & 15;
    const int h    = lane >> 4;

    float* S = smem[w];
    float* sF   = S + OFF_F;
    float* sV   = S + OFF_V;
    float* sv   = S + OFF_v;
    float* sQxu = S + OFF_QXU;
    float* sQxB = S + OFF_QXB;
    float* sQuu = S + OFF_QUU;
    float* sRf  = S + OFF_RF;
    float* sC   = S + OFF_C;
    float* sc_  = S + OFF_c;
    float* sf_  = S + OFF_f;
    float* sTau = S + OFF_TAU;
    float* sKall= S + OFF_K;
    float* sUn  = S + OFF_UN;

    for (int idx = lane; idx < 200; idx += 32) sUn[idx] = 0.f;

    // ======================= Backward Riccati — ONCE =======================
    {
        for (int idx = lane; idx < 144; idx += 32) sV[idx] = 0.f;
        if (lane < 12) sv[lane] = 0.f;

        RPre p;
        r_load(p, gC, gc, gF, gf, (TT - 1) * BB + b, lane, h, j);

        for (int t = TT - 1; t >= 0; --t) {
            reinterpret_cast<float4*>(sF)[lane] = p.F0;
            if (lane < 16) reinterpret_cast<float4*>(sF)[lane + 32] = p.F1;
            if (lane < 3)  reinterpret_cast<float4*>(sRf)[lane] = p.f4;
            float Qc[8] = {p.ca.x, p.ca.y, p.ca.z, p.ca.w,
                           p.cb.x, p.cb.y, p.cb.z, p.cb.w};
            const float cj = p.cj;
            __syncwarp();
            if (t > 0) r_load(p, gC, gc, gF, gf, (t - 1) * BB + b, lane, h, j);

            float Fc[12];
#pragma unroll
            for (int m = 0; m < 12; ++m) Fc[m] = sF[m * 16 + j];

            const float4 fv0 = *reinterpret_cast<const float4*>(sRf);
            const float4 fv1 = *reinterpret_cast<const float4*>(sRf + 4);
            const float4 fv2 = *reinterpret_cast<const float4*>(sRf + 8);

            // ---- Phase 1: W[h*6+kk][j] ; g = V f + v ; q[j]
            float W6[6], qj;
            {
                float g6[6];
#pragma unroll
                for (int kk = 0; kk < 6; ++kk) {
                    const int row = h * 6 + kk;
                    const float4* vr = reinterpret_cast<const float4*>(sV + row * 12);
                    const float4 a0 = vr[0], a1 = vr[1], a2 = vr[2];
                    W6[kk] = a0.x*Fc[0] + a0.y*Fc[1] + a0.z*Fc[2] + a0.w*Fc[3]
                           + a1.x*Fc[4] + a1.y*Fc[5] + a1.z*Fc[6] + a1.w*Fc[7]
                           + a2.x*Fc[8] + a2.y*Fc[9] + a2.z*Fc[10]+ a2.w*Fc[11];
                    g6[kk] = a0.x*fv0.x + a0.y*fv0.y + a0.z*fv0.z + a0.w*fv0.w
                           + a1.x*fv1.x + a1.y*fv1.y + a1.z*fv1.z + a1.w*fv1.w
                           + a2.x*fv2.x + a2.y*fv2.y + a2.z*fv2.z + a2.w*fv2.w
                           + sv[row];
                }
                float pj = 0.f;
#pragma unroll
                for (int kk = 0; kk < 6; ++kk) pj += Fc[h * 6 + kk] * g6[kk];
                qj = cj + pj + __shfl_xor_sync(0xffffffffu, pj, 16);
            }

            // ---- Phase 2: Qc[ii] += sum_k F[k][h*8+ii] * W[k][j]
            {
                float wlo[6], whi[6];
#pragma unroll
                for (int kk = 0; kk < 6; ++kk) {
                    const float o = __shfl_xor_sync(0xffffffffu, W6[kk], 16);
                    wlo[kk] = h ? o : W6[kk];
                    whi[kk] = h ? W6[kk] : o;
                }
#pragma unroll
                for (int k = 0; k < 12; ++k) {
                    const float wk = (k < 6) ? wlo[k] : whi[k - 6];
                    const float4* fr = reinterpret_cast<const float4*>(sF + k * 16 + h * 8);
                    const float4 fa = fr[0], fb2 = fr[1];
                    Qc[0] += fa.x * wk;  Qc[1] += fa.y * wk;
                    Qc[2] += fa.z * wk;  Qc[3] += fa.w * wk;
                    Qc[4] += fb2.x * wk; Qc[5] += fb2.y * wk;
                    Qc[6] += fb2.z * wk; Qc[7] += fb2.w * wk;
                }
            }

            // ---- stage Quu / Qxu
            if (j >= 12) {
                const int w2 = j - 12;
#pragma unroll
                for (int ii = 0; ii < 8; ++ii) {
                    float* dst;
                    if (h == 0)       dst = sQxu + ii * 4 + w2;
                    else if (ii < 4)  dst = sQxB + ii * 4 + w2;
                    else              dst = sQuu + (ii - 4) * 4 + w2;
                    *dst = Qc[ii];
                }
            }
            __syncwarp();

            // ---- Phase 3: K = -Quu^{-1} [Qux | qu] via cofactor (adjugate) solve.
            // One RCP instead of 4 pivot reciprocals; s/c terms are 12 independent
            // 2-FMA chains — far shorter critical path than Gaussian elimination.
            float K4[4], qu[4], t6, t7;
            {
#pragma unroll
                for (int u = 0; u < 4; ++u) qu[u] = __shfl_sync(0xffffffffu, qj, 12 + u);
                t6 = __shfl_xor_sync(0xffffffffu, Qc[6], 16);
                t7 = __shfl_xor_sync(0xffffffffu, Qc[7], 16);
                float r[4];
#pragma unroll
                for (int u = 0; u < 4; ++u) {
                    const float o  = __shfl_xor_sync(0xffffffffu, Qc[4 + u], 16);
                    const float rx = h ? Qc[4 + u] : o;
                    r[u] = (j < 12) ? rx : qu[u];
                }
                const float4 A0 = *reinterpret_cast<const float4*>(sQuu + 0);
                const float4 A1 = *reinterpret_cast<const float4*>(sQuu + 4);
                const float4 A2 = *reinterpret_cast<const float4*>(sQuu + 8);
                const float4 A3 = *reinterpret_cast<const float4*>(sQuu + 12);

                const float s0 = A0.x*A1.y - A0.y*A1.x;
                const float s1 = A0.x*A1.z - A0.z*A1.x;
                const float s2 = A0.x*A1.w - A0.w*A1.x;
                const float s3 = A0.y*A1.z - A0.z*A1.y;
                const float s4 = A0.y*A1.w - A0.w*A1.y;
                const float s5 = A0.z*A1.w - A0.w*A1.z;
                const float c5 = A2.z*A3.w - A2.w*A3.z;
                const float c4 = A2.y*A3.w - A2.w*A3.y;
                const float c3 = A2.y*A3.z - A2.z*A3.y;
                const float c2 = A2.x*A3.w - A2.w*A3.x;
                const float c1 = A2.x*A3.z - A2.z*A3.x;
                const float c0 = A2.x*A3.y - A2.y*A3.x;
                const float det = s0*c5 - s1*c4 + s2*c3 + s3*c2 - s4*c1 + s5*c0;
                const float invdet = 1.0f / det;

                const float r0 = r[0] * invdet;
                const float r1 = r[1] * invdet;
                const float r2 = r[2] * invdet;
                const float r3 = r[3] * invdet;

                const float sol0 = ( A1.y*c5 - A1.z*c4 + A1.w*c3) * r0
                                 + (-A0.y*c5 + A0.z*c4 - A0.w*c3) * r1
                                 + ( A3.y*s5 - A3.z*s4 + A3.w*s3) * r2
                                 + (-A2.y*s5 + A2.z*s4 - A2.w*s3) * r3;
                const float sol1 = (-A1.x*c5 + A1.z*c2 - A1.w*c1) * r0
                                 + ( A0.x*c5 - A0.z*c2 + A0.w*c1) * r1
                                 + (-A3.x*s5 + A3.z*s2 - A3.w*s1) * r2
                                 + ( A2.x*s5 - A2.z*s2 + A2.w*s1) * r3;
                const float sol2 = ( A1.x*c4 - A1.y*c2 + A1.w*c0) * r0
                                 + (-A0.x*c4 + A0.y*c2 - A0.w*c0) * r1
                                 + ( A3.x*s4 - A3.y*s2 + A3.w*s0) * r2
                                 + (-A2.x*s4 + A2.y*s2 - A2.w*s0) * r3;
                const float sol3 = (-A1.x*c3 + A1.y*c1 - A1.z*c0) * r0
                                 + ( A0.x*c3 - A0.y*c1 + A0.z*c0) * r1
                                 + (-A3.x*s3 + A3.y*s1 - A3.z*s0) * r2
                                 + ( A2.x*s3 - A2.y*s1 + A2.z*s0) * r3;
                K4[0] = -sol0; K4[1] = -sol1; K4[2] = -sol2; K4[3] = -sol3;
            }

            float* sKt = sKall + t * 52;
            if (lane < 12)
                *reinterpret_cast<float4*>(sKt + j * 4) = make_float4(K4[0], K4[1], K4[2], K4[3]);
            else if (lane == 12)
                *reinterpret_cast<float4*>(sKt + 48) = make_float4(K4[0], K4[1], K4[2], K4[3]);

            // ---- Phase 4: V = Qxx + Qxu K directly (symmetric by construction)
            if (j < 12) {
#pragma unroll
                for (int kk = 0; kk < 6; ++kk) {
                    const int i = h * 6 + kk;
                    float qij;
                    if (h == 0) qij = Qc[kk];
                    else        qij = (kk == 0) ? t6 : ((kk == 1) ? t7 : Qc[kk - 2]);
                    const float* xp = (i < 8) ? (sQxu + i * 4) : (sQxB + (i - 8) * 4);
                    const float4 x4 = *reinterpret_cast<const float4*>(xp);
                    sV[i * 12 + j] = qij + x4.x*K4[0] + x4.y*K4[1] + x4.z*K4[2] + x4.w*K4[3];
                }
                if (h == 0)
                    sv[j] = qj + K4[0]*qu[0] + K4[1]*qu[1] + K4[2]*qu[2] + K4[3]*qu[3];
            }
            __syncwarp();
        }
    }

    // ======================= 3 LQR iterations: rollout only =======================
    float cost0 = 0.f;

    for (int it = 0; it < 3; ++it) {
        const bool final_it = (it == 2);

        if (lane < 12) {
            const float x = gx0[b * 12 + lane];
#pragma unroll
            for (int a = 0; a < 5; ++a) sTau[a * 16 + lane] = x;
        }

        FPre q2;
        f_load(q2, gC, gc, gF, gf, 0 * BB + b, lane);

        float costs[5];

        if (it == 0) {
            float cA0 = 0.f, cA1 = 0.f, cA2 = 0.f;
            __syncwarp();

            for (int t = 0; t < TT; ++t) {
                {
                    const int r0 = lane >> 2, c0 = (lane & 3) * 4;
                    *reinterpret_cast<float4*>(sC + r0 * 20 + c0)       = q2.C0;
                    *reinterpret_cast<float4*>(sC + (8 + r0) * 20 + c0) = q2.C1;
                    *reinterpret_cast<float4*>(sF + r0 * 20 + c0)       = q2.F0;
                    if (lane < 16) {
                        const int rr1 = 8 + (lane >> 2);
                        *reinterpret_cast<float4*>(sF + rr1 * 20 + c0)  = q2.F1;
                    }
                    if (lane < 4) *reinterpret_cast<float4*>(sc_ + lane * 4) = q2.c4;
                    if (lane < 3) reinterpret_cast<float4*>(sf_)[lane] = q2.f4;
                }
                if (t < TT - 1) f_load(q2, gC, gc, gF, gf, (t + 1) * BB + b, lane);

                const float* sKt = sKall + t * 52;
                if (lane < 20) {
                    const int a = lane >> 2, u = lane & 3;
                    const float* xp = sTau + a * 16;
                    const float4 x0 = *reinterpret_cast<const float4*>(xp);
                    const float4 x1 = *reinterpret_cast<const float4*>(xp + 4);
                    const float4 x2 = *reinterpret_cast<const float4*>(xp + 8);
                    float ul = sKt[48 + u];
                    ul += sKt[0*4+u]*x0.x + sKt[1*4+u]*x0.y + sKt[2*4+u]*x0.z + sKt[3*4+u]*x0.w;
                    ul += sKt[4*4+u]*x1.x + sKt[5*4+u]*x1.y + sKt[6*4+u]*x1.z + sKt[7*4+u]*x1.w;
                    ul += sKt[8*4+u]*x2.x + sKt[9*4+u]*x2.y + sKt[10*4+u]*x2.z + sKt[11*4+u]*x2.w;
                    const float alpha = 1.0f / (float)(1 << a);
                    float uu = (1.0f - alpha) * sUn[t * 4 + u] + alpha * ul;
                    uu = fminf(1.0f, fmaxf(-1.0f, uu));
                    sTau[a * 16 + 12 + u] = uu;
                    g_taus[((size_t)(a * TT + t) * BB + b) * 16 + 12 + u] = uu;
                }
                __syncwarp();

#pragma unroll
                for (int rr = 0; rr < 3; ++rr) {
                    const int idx = lane + 32 * rr;
                    if (idx < 80) {
                        const int a = idx >> 4, jj = idx & 15;
                        const float4* cr = reinterpret_cast<const float4*>(sC + jj * 20);
                        const float4* tr = reinterpret_cast<const float4*>(sTau + a * 16);
                        float s = 0.f;
#pragma unroll
                        for (int iv = 0; iv < 4; ++iv) {
                            const float4 cc = cr[iv], tt = tr[iv];
                            s += cc.x*tt.x + cc.y*tt.y + cc.z*tt.z + cc.w*tt.w;
                        }
                        const float ta = sTau[a * 16 + jj];
                        const float pa = ta * (0.5f * s + sc_[jj]);
                        if (rr == 0) cA0 += pa;
                        else if (rr == 1) cA1 += pa;
                        else cA2 += pa;
                        if (a == 0 && jj < 12)
                            g_taus[((size_t)t * BB + b) * 16 + jj] = ta;
                    }
                }
                float xn0 = 0.f, xn1 = 0.f;
                {
                    int idx = lane;
                    if (idx < 60) {
                        const int a = idx / 12, s = idx - a * 12;
                        const float4* fr4 = reinterpret_cast<const float4*>(sF + s * 20);
                        const float4* tr  = reinterpret_cast<const float4*>(sTau + a * 16);
                        float v = sf_[s];
#pragma unroll
                        for (int iv = 0; iv < 4; ++iv) {
                            const float4 ff = fr4[iv], tt = tr[iv];
                            v += ff.x*tt.x + ff.y*tt.y + ff.z*tt.z + ff.w*tt.w;
                        }
                        xn0 = v;
                    }
                    idx = lane + 32;
                    if (idx < 60) {
                        const int a = idx / 12, s = idx - a * 12;
                        const float4* fr4 = reinterpret_cast<const float4*>(sF + s * 20);
                        const float4* tr  = reinterpret_cast<const float4*>(sTau + a * 16);
                        float v = sf_[s];
#pragma unroll
                        for (int iv = 0; iv < 4; ++iv) {
                            const float4 ff = fr4[iv], tt = tr[iv];
                            v += ff.x*tt.x + ff.y*tt.y + ff.z*tt.z + ff.w*tt.w;
                        }
                        xn1 = v;
                    }
                }
                __syncwarp();

                {
                    const int a0 = lane / 12, s0 = lane - a0 * 12;
                    sTau[a0 * 16 + s0] = xn0;
                    const int idx = lane + 32;
                    if (idx < 60) {
                        const int a1 = idx / 12, s1 = idx - a1 * 12;
                        sTau[a1 * 16 + s1] = xn1;
                    }
                }
                __syncwarp();
            }

#pragma unroll
            for (int d = 1; d < 16; d <<= 1) {
                cA0 += __shfl_xor_sync(0xffffffffu, cA0, d);
                cA1 += __shfl_xor_sync(0xffffffffu, cA1, d);
                cA2 += __shfl_xor_sync(0xffffffffu, cA2, d);
            }
            costs[0] = __shfl_sync(0xffffffffu, cA0, 0);
            costs[1] = __shfl_sync(0xffffffffu, cA0, 16);
            costs[2] = __shfl_sync(0xffffffffu, cA1, 0);
            costs[3] = __shfl_sync(0xffffffffu, cA1, 16);
            costs[4] = __shfl_sync(0xffffffffu, cA2, 0);
            cost0 = costs[0];
        } else {
            float cB0 = 0.f, cB1 = 0.f;
            __syncwarp();

            for (int t = 0; t < TT; ++t) {
                {
                    const int r0 = lane >> 2, c0 = (lane & 3) * 4;
                    *reinterpret_cast<float4*>(sC + r0 * 20 + c0)       = q2.C0;
                    *reinterpret_cast<float4*>(sC + (8 + r0) * 20 + c0) = q2.C1;
                    *reinterpret_cast<float4*>(sF + r0 * 20 + c0)       = q2.F0;
                    if (lane < 16) {
                        const int rr1 = 8 + (lane >> 2);
                        *reinterpret_cast<float4*>(sF + rr1 * 20 + c0)  = q2.F1;
                    }
                    if (lane < 4) *reinterpret_cast<float4*>(sc_ + lane * 4) = q2.c4;
                    if (lane < 3) reinterpret_cast<float4*>(sf_)[lane] = q2.f4;
                }
                if (t < TT - 1) f_load(q2, gC, gc, gF, gf, (t + 1) * BB + b, lane);

                const float* sKt = sKall + t * 52;
                if (lane < 16) {
                    const int a = 1 + (lane >> 2), u = lane & 3;
                    const float* xp = sTau + a * 16;
                    const float4 x0 = *reinterpret_cast<const float4*>(xp);
                    const float4 x1 = *reinterpret_cast<const float4*>(xp + 4);
                    const float4 x2 = *reinterpret_cast<const float4*>(xp + 8);
                    float ul = sKt[48 + u];
                    ul += sKt[0*4+u]*x0.x + sKt[1*4+u]*x0.y + sKt[2*4+u]*x0.z + sKt[3*4+u]*x0.w;
                    ul += sKt[4*4+u]*x1.x + sKt[5*4+u]*x1.y + sKt[6*4+u]*x1.z + sKt[7*4+u]*x1.w;
                    ul += sKt[8*4+u]*x2.x + sKt[9*4+u]*x2.y + sKt[10*4+u]*x2.z + sKt[11*4+u]*x2.w;
                    const float alpha = 1.0f / (float)(1 << a);
                    float uu = (1.0f - alpha) * sUn[t * 4 + u] + alpha * ul;
                    uu = fminf(1.0f, fmaxf(-1.0f, uu));
                    sTau[a * 16 + 12 + u] = uu;
                    g_taus[((size_t)(a * TT + t) * BB + b) * 16 + 12 + u] = uu;
                }
                __syncwarp();

#pragma unroll
                for (int rr = 0; rr < 2; ++rr) {
                    const int idx = lane + 32 * rr;
                    const int a = 1 + (idx >> 4), jj = idx & 15;
                    const float4* cr = reinterpret_cast<const float4*>(sC + jj * 20);
                    const float4* tr = reinterpret_cast<const float4*>(sTau + a * 16);
                    float s = 0.f;
#pragma unroll
                    for (int iv = 0; iv < 4; ++iv) {
                        const float4 cc = cr[iv], tt = tr[iv];
                        s += cc.x*tt.x + cc.y*tt.y + cc.z*tt.z + cc.w*tt.w;
                    }
                    const float ta = sTau[a * 16 + jj];
                    const float pa = ta * (0.5f * s + sc_[jj]);
                    if (rr == 0) cB0 += pa; else cB1 += pa;
                    if (final_it && jj < 12)
                        g_taus[((size_t)(a * TT + t) * BB + b) * 16 + jj] = ta;
                }
                float xn0 = 0.f, xn1 = 0.f;
                {
                    int idx = lane;
                    if (idx < 48) {
                        const int a = 1 + idx / 12, s = idx - (a - 1) * 12;
                        const float4* fr4 = reinterpret_cast<const float4*>(sF + s * 20);
                        const float4* tr  = reinterpret_cast<const float4*>(sTau + a * 16);
                        float v = sf_[s];
#pragma unroll
                        for (int iv = 0; iv < 4; ++iv) {
                            const float4 ff = fr4[iv], tt = tr[iv];
                            v += ff.x*tt.x + ff.y*tt.y + ff.z*tt.z + ff.w*tt.w;
                        }
                        xn0 = v;
                    }
                    idx = lane + 32;
                    if (idx < 48) {
                        const int a = 1 + idx / 12, s = idx - (a - 1) * 12;
                        const float4* fr4 = reinterpret_cast<const float4*>(sF + s * 20);
                        const float4* tr  = reinterpret_cast<const float4*>(sTau + a * 16);
                        float v = sf_[s];
#pragma unroll
                        for (int iv = 0; iv < 4; ++iv) {
                            const float4 ff = fr4[iv], tt = tr[iv];
                            v += ff.x*tt.x + ff.y*tt.y + ff.z*tt.z + ff.w*tt.w;
                        }
                        xn1 = v;
                    }
                }
                __syncwarp();

                {
                    const int idx0 = lane;
                    if (idx0 < 48) {
                        const int a0 = 1 + idx0 / 12, s0 = idx0 - (a0 - 1) * 12;
                        sTau[a0 * 16 + s0] = xn0;
                    }
                    const int idx1 = lane + 32;
                    if (idx1 < 48) {
                        const int a1 = 1 + idx1 / 12, s1 = idx1 - (a1 - 1) * 12;
                        sTau[a1 * 16 + s1] = xn1;
                    }
                }
                __syncwarp();
            }

#pragma unroll
            for (int d = 1; d < 16; d <<= 1) {
                cB0 += __shfl_xor_sync(0xffffffffu, cB0, d);
                cB1 += __shfl_xor_sync(0xffffffffu, cB1, d);
            }
            costs[0] = cost0;
            costs[1] = __shfl_sync(0xffffffffu, cB0, 0);
            costs[2] = __shfl_sync(0xffffffffu, cB0, 16);
            costs[3] = __shfl_sync(0xffffffffu, cB1, 0);
            costs[4] = __shfl_sync(0xffffffffu, cB1, 16);
        }

        int bi = 0;
        {
            float bc = costs[0];
#pragma unroll
            for (int a = 1; a < 5; ++a)
                if (costs[a] < bc) { bc = costs[a]; bi = a; }
        }

        if (!final_it) {
            for (int idx = lane; idx < 200; idx += 32) {
                const int t = idx >> 2, u = idx & 3;
                sUn[idx] = g_taus[((size_t)(bi * TT + t) * BB + b) * 16 + 12 + u];
            }
        } else {
            for (int idx = lane; idx < 800; idx += 32) {
                const int t = idx >> 4, i = idx & 15;
                out[((size_t)t * BB + b) * 16 + i] =
                    g_taus[((size_t)(bi * TT + t) * BB + b) * 16 + i];
            }
        }
        __syncwarp();
    }
}

extern "C" void kernel_launch(void* const* d_in, const int* in_sizes, int n_in,
                              void* d_out, int out_size)
{
    const float *x0 = nullptr, *C = nullptr, *c = nullptr, *F = nullptr, *f = nullptr;
    for (int i = 0; i < n_in; ++i) {
        switch (in_sizes[i]) {
            case BB * 12:       x0 = (const float*)d_in[i]; break;
            case TT * BB * 256: C  = (const float*)d_in[i]; break;
            case TT * BB * 16:  c  = (const float*)d_in[i]; break;
            case TT * BB * 192: F  = (const float*)d_in[i]; break;
            case TT * BB * 12:  f  = (const float*)d_in[i]; break;
        }
    }
    ilqr_fused_kernel<<<BB / WPB, 32 * WPB>>>(C, c, F, f, x0, (float*)d_out);
}

// round 17
// speedup vs baseline: 1.0817x; 1.0817x over previous
#include <cuda_runtime.h>

#define TT  50
#define BB  2048
#define NLS 5
#define WPB 2

__device__ __align__(16) float g_taus[NLS * TT * BB * 16];  // [a][t][b][16]

// ---- per-warp smem layout (float offsets) ----
#define OFF_F    0
#define OFF_V    240
#define OFF_v    384
#define OFF_QXU  416
#define OFF_QXB  464
#define OFF_QUU  480
#define OFF_RF   656
// rollout overlays
#define OFF_C    240
#define OFF_c    560
#define OFF_f    576
#define OFF_TAU  592    // 80 [a][16]: x state lives in slots 0..11, u in 12..15
// persistent
#define OFF_UN   736
#define OFF_K    936
#define WF       3536

struct RPre { float4 F0, F1, f4, ca, cb; float cj; };

__device__ __forceinline__ void r_load(RPre& p,
    const float* __restrict__ gC, const float* __restrict__ gc,
    const float* __restrict__ gF, const float* __restrict__ gf,
    int base, int lane, int h, int j)
{
    const float4* F4 = reinterpret_cast<const float4*>(gF) + (size_t)base * 48;
    p.F0 = F4[lane];
    if (lane < 16) p.F1 = F4[lane + 32];
    const float4* C4 = reinterpret_cast<const float4*>(gC) + (size_t)base * 64;
    p.ca = C4[j * 4 + h * 2];
    p.cb = C4[j * 4 + h * 2 + 1];
    p.cj = gc[(size_t)base * 16 + j];
    if (lane < 3) p.f4 = reinterpret_cast<const float4*>(gf + (size_t)base * 12)[lane];
}

struct FPre { float4 C0, C1, F0, F1, c4, f4; };

__device__ __forceinline__ void f_load(FPre& p,
    const float* __restrict__ gC, const float* __restrict__ gc,
    const float* __restrict__ gF, const float* __restrict__ gf,
    int base, int lane)
{
    const float4* C4 = reinterpret_cast<const float4*>(gC) + (size_t)base * 64;
    p.C0 = C4[lane];
    p.C1 = C4[lane + 32];
    const float4* F4 = reinterpret_cast<const float4*>(gF) + (size_t)base * 48;
    p.F0 = F4[lane];
    if (lane < 16) p.F1 = F4[lane + 32];
    if (lane < 4)  p.c4 = reinterpret_cast<const float4*>(gc)[(size_t)base * 4 + lane];
    if (lane < 3)  p.f4 = reinterpret_cast<const float4*>(gf + (size_t)base * 12)[lane];
}

__global__ void __launch_bounds__(32 * WPB, 7) ilqr_fused_kernel(
    const float* __restrict__ gC, const float* __restrict__ gc,
    const float* __restrict__ gF, const float* __restrict__ gf,
    const float* __restrict__ gx0, float* __restrict__ out)
{
    __shared__ __align__(16) float smem[WPB][WF];
    const int w    = threadIdx.x >> 5;
    const int lane = threadIdx.x & 31;
    const int b    = blockIdx.x * WPB + w;
    const int j    = lane & 15;
    const int h    = lane >> 4;

    float* S = smem[w];
    float* sF   = S + OFF_F;
    float* sV   = S + OFF_V;
    float* sv   = S + OFF_v;
    float* sQxu = S + OFF_QXU;
    float* sQxB = S + OFF_QXB;
    float* sQuu = S + OFF_QUU;
    float* sRf  = S + OFF_RF;
    float* sC   = S + OFF_C;
    float* sc_  = S + OFF_c;
    float* sf_  = S + OFF_f;
    float* sTau = S + OFF_TAU;
    float* sKall= S + OFF_K;
    float* sUn  = S + OFF_UN;

    for (int idx = lane; idx < 200; idx += 32) sUn[idx] = 0.f;

    // ======================= Backward Riccati — ONCE (R15 verbatim) ============
    {
        for (int idx = lane; idx < 144; idx += 32) sV[idx] = 0.f;
        if (lane < 12) sv[lane] = 0.f;

        RPre p;
        r_load(p, gC, gc, gF, gf, (TT - 1) * BB + b, lane, h, j);

        for (int t = TT - 1; t >= 0; --t) {
            reinterpret_cast<float4*>(sF)[lane] = p.F0;
            if (lane < 16) reinterpret_cast<float4*>(sF)[lane + 32] = p.F1;
            if (lane < 3)  reinterpret_cast<float4*>(sRf)[lane] = p.f4;
            float Qc[8] = {p.ca.x, p.ca.y, p.ca.z, p.ca.w,
                           p.cb.x, p.cb.y, p.cb.z, p.cb.w};
            const float cj = p.cj;
            __syncwarp();
            if (t > 0) r_load(p, gC, gc, gF, gf, (t - 1) * BB + b, lane, h, j);

            float Fc[12];
#pragma unroll
            for (int m = 0; m < 12; ++m) Fc[m] = sF[m * 16 + j];

            const float4 fv0 = *reinterpret_cast<const float4*>(sRf);
            const float4 fv1 = *reinterpret_cast<const float4*>(sRf + 4);
            const float4 fv2 = *reinterpret_cast<const float4*>(sRf + 8);

            float W6[6], qj;
            {
                float g6[6];
#pragma unroll
                for (int kk = 0; kk < 6; ++kk) {
                    const int row = h * 6 + kk;
                    const float4* vr = reinterpret_cast<const float4*>(sV + row * 12);
                    const float4 a0 = vr[0], a1 = vr[1], a2 = vr[2];
                    W6[kk] = a0.x*Fc[0] + a0.y*Fc[1] + a0.z*Fc[2] + a0.w*Fc[3]
                           + a1.x*Fc[4] + a1.y*Fc[5] + a1.z*Fc[6] + a1.w*Fc[7]
                           + a2.x*Fc[8] + a2.y*Fc[9] + a2.z*Fc[10]+ a2.w*Fc[11];
                    g6[kk] = a0.x*fv0.x + a0.y*fv0.y + a0.z*fv0.z + a0.w*fv0.w
                           + a1.x*fv1.x + a1.y*fv1.y + a1.z*fv1.z + a1.w*fv1.w
                           + a2.x*fv2.x + a2.y*fv2.y + a2.z*fv2.z + a2.w*fv2.w
                           + sv[row];
                }
                float pj = 0.f;
#pragma unroll
                for (int kk = 0; kk < 6; ++kk) pj += Fc[h * 6 + kk] * g6[kk];
                qj = cj + pj + __shfl_xor_sync(0xffffffffu, pj, 16);
            }

            {
                float wlo[6], whi[6];
#pragma unroll
                for (int kk = 0; kk < 6; ++kk) {
                    const float o = __shfl_xor_sync(0xffffffffu, W6[kk], 16);
                    wlo[kk] = h ? o : W6[kk];
                    whi[kk] = h ? W6[kk] : o;
                }
#pragma unroll
                for (int k = 0; k < 12; ++k) {
                    const float wk = (k < 6) ? wlo[k] : whi[k - 6];
                    const float4* fr = reinterpret_cast<const float4*>(sF + k * 16 + h * 8);
                    const float4 fa = fr[0], fb2 = fr[1];
                    Qc[0] += fa.x * wk;  Qc[1] += fa.y * wk;
                    Qc[2] += fa.z * wk;  Qc[3] += fa.w * wk;
                    Qc[4] += fb2.x * wk; Qc[5] += fb2.y * wk;
                    Qc[6] += fb2.z * wk; Qc[7] += fb2.w * wk;
                }
            }

            if (j >= 12) {
                const int w2 = j - 12;
#pragma unroll
                for (int ii = 0; ii < 8; ++ii) {
                    float* dst;
                    if (h == 0)       dst = sQxu + ii * 4 + w2;
                    else if (ii < 4)  dst = sQxB + ii * 4 + w2;
                    else              dst = sQuu + (ii - 4) * 4 + w2;
                    *dst = Qc[ii];
                }
            }
            __syncwarp();

            // ---- Phase 3: Gaussian elimination (R15)
            float K4[4], qu[4], t6, t7;
            {
#pragma unroll
                for (int u = 0; u < 4; ++u) qu[u] = __shfl_sync(0xffffffffu, qj, 12 + u);
                t6 = __shfl_xor_sync(0xffffffffu, Qc[6], 16);
                t7 = __shfl_xor_sync(0xffffffffu, Qc[7], 16);
                float r[4];
#pragma unroll
                for (int u = 0; u < 4; ++u) {
                    const float o  = __shfl_xor_sync(0xffffffffu, Qc[4 + u], 16);
                    const float rx = h ? Qc[4 + u] : o;
                    r[u] = (j < 12) ? rx : qu[u];
                }
                const float4 A0 = *reinterpret_cast<const float4*>(sQuu + 0);
                const float4 A1 = *reinterpret_cast<const float4*>(sQuu + 4);
                const float4 A2 = *reinterpret_cast<const float4*>(sQuu + 8);
                const float4 A3 = *reinterpret_cast<const float4*>(sQuu + 12);
                float A[4][4] = {{A0.x,A0.y,A0.z,A0.w},{A1.x,A1.y,A1.z,A1.w},
                                 {A2.x,A2.y,A2.z,A2.w},{A3.x,A3.y,A3.z,A3.w}};
#pragma unroll
                for (int pp = 0; pp < 4; ++pp) {
                    const float inv = 1.0f / A[pp][pp];
                    r[pp] *= inv;
#pragma unroll
                    for (int w2 = 0; w2 < 4; ++w2) if (w2 > pp) A[pp][w2] *= inv;
#pragma unroll
                    for (int u = 0; u < 4; ++u) if (u > pp) {
                        const float mu = A[u][pp];
                        r[u] -= mu * r[pp];
#pragma unroll
                        for (int w2 = 0; w2 < 4; ++w2) if (w2 > pp) A[u][w2] -= mu * A[pp][w2];
                    }
                }
#pragma unroll
                for (int pp = 3; pp >= 1; --pp)
#pragma unroll
                    for (int u = 0; u < 4; ++u) if (u < pp) r[u] -= A[u][pp] * r[pp];
#pragma unroll
                for (int u = 0; u < 4; ++u) K4[u] = -r[u];
            }

            float* sKt = sKall + t * 52;
            if (lane < 12)
                *reinterpret_cast<float4*>(sKt + j * 4) = make_float4(K4[0], K4[1], K4[2], K4[3]);
            else if (lane == 12)
                *reinterpret_cast<float4*>(sKt + 48) = make_float4(K4[0], K4[1], K4[2], K4[3]);

            if (j < 12) {
#pragma unroll
                for (int kk = 0; kk < 6; ++kk) {
                    const int i = h * 6 + kk;
                    float qij;
                    if (h == 0) qij = Qc[kk];
                    else        qij = (kk == 0) ? t6 : ((kk == 1) ? t7 : Qc[kk - 2]);
                    const float* xp = (i < 8) ? (sQxu + i * 4) : (sQxB + (i - 8) * 4);
                    const float4 x4 = *reinterpret_cast<const float4*>(xp);
                    sV[i * 12 + j] = qij + x4.x*K4[0] + x4.y*K4[1] + x4.z*K4[2] + x4.w*K4[3];
                }
                if (h == 0)
                    sv[j] = qj + K4[0]*qu[0] + K4[1]*qu[1] + K4[2]*qu[2] + K4[3]*qu[3];
            }
            __syncwarp();
        }
    }

    // ======================= 3 LQR iterations: rollout only =======================
    float cost0 = 0.f;

    for (int it = 0; it < 3; ++it) {
        const bool final_it = (it == 2);

        if (lane < 12) {
            const float x = gx0[b * 12 + lane];
#pragma unroll
            for (int a = 0; a < 5; ++a) sTau[a * 16 + lane] = x;
        }

        FPre q2;
        f_load(q2, gC, gc, gF, gf, 0 * BB + b, lane);

        float costs[5];

        if (it == 0) {
            float cA0 = 0.f, cA1 = 0.f, cA2 = 0.f;
            __syncwarp();

            for (int t = 0; t < TT; ++t) {
                {
                    const int r0 = lane >> 2, c0 = (lane & 3) * 4;
                    *reinterpret_cast<float4*>(sC + r0 * 20 + c0)       = q2.C0;
                    *reinterpret_cast<float4*>(sC + (8 + r0) * 20 + c0) = q2.C1;
                    *reinterpret_cast<float4*>(sF + r0 * 20 + c0)       = q2.F0;
                    if (lane < 16) {
                        const int rr1 = 8 + (lane >> 2);
                        *reinterpret_cast<float4*>(sF + rr1 * 20 + c0)  = q2.F1;
                    }
                    if (lane < 4) *reinterpret_cast<float4*>(sc_ + lane * 4) = q2.c4;
                    if (lane < 3) reinterpret_cast<float4*>(sf_)[lane] = q2.f4;
                }
                if (t < TT - 1) f_load(q2, gC, gc, gF, gf, (t + 1) * BB + b, lane);

                const float* sKt = sKall + t * 52;
                if (lane < 20) {
                    const int a = lane >> 2, u = lane & 3;
                    const float* xp = sTau + a * 16;
                    const float4 x0 = *reinterpret_cast<const float4*>(xp);
                    const float4 x1 = *reinterpret_cast<const float4*>(xp + 4);
                    const float4 x2 = *reinterpret_cast<const float4*>(xp + 8);
                    float ul = sKt[48 + u];
                    ul += sKt[0*4+u]*x0.x + sKt[1*4+u]*x0.y + sKt[2*4+u]*x0.z + sKt[3*4+u]*x0.w;
                    ul += sKt[4*4+u]*x1.x + sKt[5*4+u]*x1.y + sKt[6*4+u]*x1.z + sKt[7*4+u]*x1.w;
                    ul += sKt[8*4+u]*x2.x + sKt[9*4+u]*x2.y + sKt[10*4+u]*x2.z + sKt[11*4+u]*x2.w;
                    const float alpha = 1.0f / (float)(1 << a);
                    float uu = (1.0f - alpha) * sUn[t * 4 + u] + alpha * ul;
                    uu = fminf(1.0f, fmaxf(-1.0f, uu));
                    sTau[a * 16 + 12 + u] = uu;
                    g_taus[((size_t)(a * TT + t) * BB + b) * 16 + 12 + u] = uu;
                }
                __syncwarp();

#pragma unroll
                for (int rr = 0; rr < 3; ++rr) {
                    const int idx = lane + 32 * rr;
                    if (idx < 80) {
                        const int a = idx >> 4, jj = idx & 15;
                        const float4* cr = reinterpret_cast<const float4*>(sC + jj * 20);
                        const float4* tr = reinterpret_cast<const float4*>(sTau + a * 16);
                        float s = 0.f;
#pragma unroll
                        for (int iv = 0; iv < 4; ++iv) {
                            const float4 cc = cr[iv], tt = tr[iv];
                            s += cc.x*tt.x + cc.y*tt.y + cc.z*tt.z + cc.w*tt.w;
                        }
                        const float ta = sTau[a * 16 + jj];
                        const float pa = ta * (0.5f * s + sc_[jj]);
                        if (rr == 0) cA0 += pa;
                        else if (rr == 1) cA1 += pa;
                        else cA2 += pa;
                        if (a == 0 && jj < 12)
                            g_taus[((size_t)t * BB + b) * 16 + jj] = ta;
                    }
                }
                float xn0 = 0.f, xn1 = 0.f;
                {
                    int idx = lane;
                    if (idx < 60) {
                        const int a = idx / 12, s = idx - a * 12;
                        const float4* fr4 = reinterpret_cast<const float4*>(sF + s * 20);
                        const float4* tr  = reinterpret_cast<const float4*>(sTau + a * 16);
                        float v = sf_[s];
#pragma unroll
                        for (int iv = 0; iv < 4; ++iv) {
                            const float4 ff = fr4[iv], tt = tr[iv];
                            v += ff.x*tt.x + ff.y*tt.y + ff.z*tt.z + ff.w*tt.w;
                        }
                        xn0 = v;
                    }
                    idx = lane + 32;
                    if (idx < 60) {
                        const int a = idx / 12, s = idx - a * 12;
                        const float4* fr4 = reinterpret_cast<const float4*>(sF + s * 20);
                        const float4* tr  = reinterpret_cast<const float4*>(sTau + a * 16);
                        float v = sf_[s];
#pragma unroll
                        for (int iv = 0; iv < 4; ++iv) {
                            const float4 ff = fr4[iv], tt = tr[iv];
                            v += ff.x*tt.x + ff.y*tt.y + ff.z*tt.z + ff.w*tt.w;
                        }
                        xn1 = v;
                    }
                }
                __syncwarp();

                {
                    const int a0 = lane / 12, s0 = lane - a0 * 12;
                    sTau[a0 * 16 + s0] = xn0;
                    const int idx = lane + 32;
                    if (idx < 60) {
                        const int a1 = idx / 12, s1 = idx - a1 * 12;
                        sTau[a1 * 16 + s1] = xn1;
                    }
                }
                __syncwarp();
            }

#pragma unroll
            for (int d = 1; d < 16; d <<= 1) {
                cA0 += __shfl_xor_sync(0xffffffffu, cA0, d);
                cA1 += __shfl_xor_sync(0xffffffffu, cA1, d);
                cA2 += __shfl_xor_sync(0xffffffffu, cA2, d);
            }
            costs[0] = __shfl_sync(0xffffffffu, cA0, 0);
            costs[1] = __shfl_sync(0xffffffffu, cA0, 16);
            costs[2] = __shfl_sync(0xffffffffu, cA1, 0);
            costs[3] = __shfl_sync(0xffffffffu, cA1, 16);
            costs[4] = __shfl_sync(0xffffffffu, cA2, 0);
            cost0 = costs[0];
        } else {
            float cB0 = 0.f, cB1 = 0.f;
            __syncwarp();

            for (int t = 0; t < TT; ++t) {
                {
                    const int r0 = lane >> 2, c0 = (lane & 3) * 4;
                    *reinterpret_cast<float4*>(sC + r0 * 20 + c0)       = q2.C0;
                    *reinterpret_cast<float4*>(sC + (8 + r0) * 20 + c0) = q2.C1;
                    *reinterpret_cast<float4*>(sF + r0 * 20 + c0)       = q2.F0;
                    if (lane < 16) {
                        const int rr1 = 8 + (lane >> 2);
                        *reinterpret_cast<float4*>(sF + rr1 * 20 + c0)  = q2.F1;
                    }
                    if (lane < 4) *reinterpret_cast<float4*>(sc_ + lane * 4) = q2.c4;
                    if (lane < 3) reinterpret_cast<float4*>(sf_)[lane] = q2.f4;
                }
                if (t < TT - 1) f_load(q2, gC, gc, gF, gf, (t + 1) * BB + b, lane);

                const float* sKt = sKall + t * 52;
                if (lane < 16) {
                    const int a = 1 + (lane >> 2), u = lane & 3;
                    const float* xp = sTau + a * 16;
                    const float4 x0 = *reinterpret_cast<const float4*>(xp);
                    const float4 x1 = *reinterpret_cast<const float4*>(xp + 4);
                    const float4 x2 = *reinterpret_cast<const float4*>(xp + 8);
                    float ul = sKt[48 + u];
                    ul += sKt[0*4+u]*x0.x + sKt[1*4+u]*x0.y + sKt[2*4+u]*x0.z + sKt[3*4+u]*x0.w;
                    ul += sKt[4*4+u]*x1.x + sKt[5*4+u]*x1.y + sKt[6*4+u]*x1.z + sKt[7*4+u]*x1.w;
                    ul += sKt[8*4+u]*x2.x + sKt[9*4+u]*x2.y + sKt[10*4+u]*x2.z + sKt[11*4+u]*x2.w;
                    const float alpha = 1.0f / (float)(1 << a);
                    float uu = (1.0f - alpha) * sUn[t * 4 + u] + alpha * ul;
                    uu = fminf(1.0f, fmaxf(-1.0f, uu));
                    sTau[a * 16 + 12 + u] = uu;
                    g_taus[((size_t)(a * TT + t) * BB + b) * 16 + 12 + u] = uu;
                }
                __syncwarp();

#pragma unroll
                for (int rr = 0; rr < 2; ++rr) {
                    const int idx = lane + 32 * rr;
                    const int a = 1 + (idx >> 4), jj = idx & 15;
                    const float4* cr = reinterpret_cast<const float4*>(sC + jj * 20);
                    const float4* tr = reinterpret_cast<const float4*>(sTau + a * 16);
                    float s = 0.f;
#pragma unroll
                    for (int iv = 0; iv < 4; ++iv) {
                        const float4 cc = cr[iv], tt = tr[iv];
                        s += cc.x*tt.x + cc.y*tt.y + cc.z*tt.z + cc.w*tt.w;
                    }
                    const float ta = sTau[a * 16 + jj];
                    const float pa = ta * (0.5f * s + sc_[jj]);
                    if (rr == 0) cB0 += pa; else cB1 += pa;
                    if (final_it && jj < 12)
                        g_taus[((size_t)(a * TT + t) * BB + b) * 16 + jj] = ta;
                }
                float xn0 = 0.f, xn1 = 0.f;
                {
                    int idx = lane;
                    if (idx < 48) {
                        const int a = 1 + idx / 12, s = idx - (a - 1) * 12;
                        const float4* fr4 = reinterpret_cast<const float4*>(sF + s * 20);
                        const float4* tr  = reinterpret_cast<const float4*>(sTau + a * 16);
                        float v = sf_[s];
#pragma unroll
                        for (int iv = 0; iv < 4; ++iv) {
                            const float4 ff = fr4[iv], tt = tr[iv];
                            v += ff.x*tt.x + ff.y*tt.y + ff.z*tt.z + ff.w*tt.w;
                        }
                        xn0 = v;
                    }
                    idx = lane + 32;
                    if (idx < 48) {
                        const int a = 1 + idx / 12, s = idx - (a - 1) * 12;
                        const float4* fr4 = reinterpret_cast<const float4*>(sF + s * 20);
                        const float4* tr  = reinterpret_cast<const float4*>(sTau + a * 16);
                        float v = sf_[s];
#pragma unroll
                        for (int iv = 0; iv < 4; ++iv) {
                            const float4 ff = fr4[iv], tt = tr[iv];
                            v += ff.x*tt.x + ff.y*tt.y + ff.z*tt.z + ff.w*tt.w;
                        }
                        xn1 = v;
                    }
                }
                __syncwarp();

                {
                    const int idx0 = lane;
                    if (idx0 < 48) {
                        const int a0 = 1 + idx0 / 12, s0 = idx0 - (a0 - 1) * 12;
                        sTau[a0 * 16 + s0] = xn0;
                    }
                    const int idx1 = lane + 32;
                    if (idx1 < 48) {
                        const int a1 = 1 + idx1 / 12, s1 = idx1 - (a1 - 1) * 12;
                        sTau[a1 * 16 + s1] = xn1;
                    }
                }
                __syncwarp();
            }

#pragma unroll
            for (int d = 1; d < 16; d <<= 1) {
                cB0 += __shfl_xor_sync(0xffffffffu, cB0, d);
                cB1 += __shfl_xor_sync(0xffffffffu, cB1, d);
            }
            costs[0] = cost0;
            costs[1] = __shfl_sync(0xffffffffu, cB0, 0);
            costs[2] = __shfl_sync(0xffffffffu, cB0, 16);
            costs[3] = __shfl_sync(0xffffffffu, cB1, 0);
            costs[4] = __shfl_sync(0xffffffffu, cB1, 16);
        }

        int bi = 0;
        {
            float bc = costs[0];
#pragma unroll
            for (int a = 1; a < 5; ++a)
                if (costs[a] < bc) { bc = costs[a]; bi = a; }
        }

        if (!final_it) {
            // vectorized u_nom gather: 50 float4s (16B-aligned: offset*16+12)
            for (int t4 = lane; t4 < TT; t4 += 32) {
                const float4 v = *reinterpret_cast<const float4*>(
                    g_taus + ((size_t)(bi * TT + t4) * BB + b) * 16 + 12);
                *reinterpret_cast<float4*>(sUn + t4 * 4) = v;
            }
        } else {
            // vectorized final output: 200 float4s
            for (int idx = lane; idx < 200; idx += 32) {
                const int t = idx >> 2, i4 = (idx & 3) * 4;
                const float4 v = *reinterpret_cast<const float4*>(
                    g_taus + ((size_t)(bi * TT + t) * BB + b) * 16 + i4);
                *reinterpret_cast<float4*>(out + ((size_t)t * BB + b) * 16 + i4) = v;
            }
        }
        __syncwarp();
    }
}

extern "C" void kernel_launch(void* const* d_in, const int* in_sizes, int n_in,
                              void* d_out, int out_size)
{
    const float *x0 = nullptr, *C = nullptr, *c = nullptr, *F = nullptr, *f = nullptr;
    for (int i = 0; i < n_in; ++i) {
        switch (in_sizes[i]) {
            case BB * 12:       x0 = (const float*)d_in[i]; break;
            case TT * BB * 256: C  = (const float*)d_in[i]; break;
            case TT * BB * 16:  c  = (const float*)d_in[i]; break;
            case TT * BB * 192: F  = (const float*)d_in[i]; break;
            case TT * BB * 12:  f  = (const float*)d_in[i]; break;
        }
    }
    ilqr_fused_kernel<<<BB / WPB, 32 * WPB>>>(C, c, F, f, x0, (float*)d_out);
}